// round 12
// baseline (speedup 1.0000x reference)
#include <cuda_runtime.h>
#include <cuda_bf16.h>

// MomentumLSTM v11: v10 (512 thr, 128 regs, occ 4 warps/SMSP; best 2115us) +
// corrected LDS.128 fusion:
//  - weights: per-k row split into [j][i0,i1,f0,f1] | [j][g0,g1,o0,o1] blocks,
//    lane reads 16B/block (512B span = 4 wf, same as v6's LDS.64s, half the issues)
//  - h/x: broadcast LDS.128 fetches 2 batch pairs (state stride 10 -> 12 for 16B align)

#define BATCH  32768
#define TT     60
#define DD     7
#define H1     64
#define G1     256
#define H2     32
#define G2     128
#define NT     512
#define GRID   152
#define TB     8                 // batches per warp-task
#define NTASKS (BATCH / TB)      // 4096
#define WSLOTS (GRID * 16)       // 2432
#define HS1    12                // [64][12] per-warp h1 slab, 16B-aligned rows
#define HS2    12                // [32][12]
#define XS     8                 // [7][8] (32B rows, 16B-aligned)

// SMEM float offsets
#define OFF_W1T 0                // [71][256] blocked: [k][j][i0,i1,f0,f1] | [k][j][g0,g1,o0,o1]
#define OFF_W2T 18176            // [96][128] blocked same way (j=0..15)
#define OFF_B1  30464            // [256] linear
#define OFF_B2  30720            // [128] linear
#define OFF_H1  30848            // 16 x 768
#define OFF_H2  43136            // 16 x 384
#define OFF_X   49280            // 16 x 64
#define SMEM_FLOATS 50304
#define SMEM_BYTES  (SMEM_FLOATS * 4)   // 201216

typedef unsigned long long u64t;

__device__ __forceinline__ u64t pk2(float a, float b) {
    u64t r; asm("mov.b64 %0, {%1, %2};" : "=l"(r) : "f"(a), "f"(b)); return r;
}
__device__ __forceinline__ void upk(u64t v, float& lo, float& hi) {
    asm("mov.b64 {%0, %1}, %2;" : "=f"(lo), "=f"(hi) : "l"(v));
}
__device__ __forceinline__ u64t fma2(u64t a, u64t b, u64t c) {
    u64t d; asm("fma.rn.f32x2 %0, %1, %2, %3;" : "=l"(d) : "l"(a), "l"(b), "l"(c)); return d;
}
__device__ __forceinline__ u64t lds64(const float* p) {
    return *reinterpret_cast<const u64t*>(p);
}
__device__ __forceinline__ void sts64(float* p, u64t v) {
    *reinterpret_cast<u64t*>(p) = v;
}
__device__ __forceinline__ ulonglong2 lds128(const float* p) {
    return *reinterpret_cast<const ulonglong2*>(p);
}
__device__ __forceinline__ float tanha(float x) {
    float y; asm("tanh.approx.f32 %0, %1;" : "=f"(y) : "f"(x)); return y;
}
// acc already holds x/2 (weights pre-scaled): sigmoid(x) = 0.5*tanh(x/2)+0.5
__device__ __forceinline__ float sig_h(float halfx) {
    return fmaf(0.5f, tanha(halfx), 0.5f);
}
__device__ __forceinline__ float sigx(float x) {   // exact, output only
    return __fdividef(1.0f, 1.0f + __expf(-x));
}

__global__ void __launch_bounds__(NT, 1)
momentum_lstm_kernel(const float* __restrict__ x,
                     const float* __restrict__ Wih1, const float* __restrict__ Whh1,
                     const float* __restrict__ bih1, const float* __restrict__ bhh1,
                     const float* __restrict__ Wih2, const float* __restrict__ Whh2,
                     const float* __restrict__ bih2, const float* __restrict__ bhh2,
                     const float* __restrict__ Wd,  const float* __restrict__ bd,
                     const float* __restrict__ Wo,  const float* __restrict__ bo,
                     float* __restrict__ out)
{
    extern __shared__ float sm[];
    float* sW1T = sm + OFF_W1T;
    float* sW2T = sm + OFF_W2T;
    float* sB1  = sm + OFF_B1;
    float* sB2  = sm + OFF_B2;

    const int tid  = threadIdx.x;
    const int lane = tid & 31;
    const int wid  = tid >> 5;

    float* sH1w = sm + OFF_H1 + wid * (H1 * HS1);
    float* sH2w = sm + OFF_H2 + wid * (H2 * HS2);
    float* sXw  = sm + OFF_X  + wid * 64;

    // ------- staging: blocked layout + pre-scale i/f/o by 0.5 (gate order i,f,g,o) -------
    // layer1 row (256 floats): [0..127]  = j*4 + {i(2j),i(2j+1),f(2j),f(2j+1)}
    //                          [128..255]= j*4 + {g(2j),g(2j+1),o(2j),o(2j+1)}
    for (int i = tid; i < (DD + H1) * G1; i += NT) {
        int r = i >> 8, off = i & 255;
        int half = off >> 7, j = (off >> 2) & 31, s = off & 3;
        int g = half * 2 + (s >> 1);
        int unit = 2 * j + (s & 1);
        int grow = g * H1 + unit;
        float v = (r < DD) ? Wih1[grow * DD + r] : Whh1[grow * H1 + (r - DD)];
        sW1T[i] = ((g == 2) ? 1.0f : 0.5f) * v;
    }
    // layer2 row (128 floats): [0..63] = j*4 + {i,i,f,f}(2j,2j+1), [64..127] = {g,g,o,o}
    for (int i = tid; i < (H1 + H2) * G2; i += NT) {
        int k = i >> 7, off = i & 127;
        int half = off >> 6, j = (off >> 2) & 15, s = off & 3;
        int g = half * 2 + (s >> 1);
        int unit = 2 * j + (s & 1);
        int grow = g * H2 + unit;
        float v = (k < H1) ? Wih2[grow * H1 + k] : Whh2[grow * H2 + (k - H1)];
        sW2T[i] = ((g == 2) ? 1.0f : 0.5f) * v;
    }
    if (tid < G1) {
        float s = ((tid >> 6) == 2) ? 1.0f : 0.5f;
        sB1[tid] = s * (bih1[tid] + bhh1[tid]);
    }
    if (tid < G2) {
        float s = ((tid >> 5) == 2) ? 1.0f : 0.5f;
        sB2[tid] = s * (bih2[tid] + bhh2[tid]);
    }
    __syncthreads();

    // ---------------- warp-local tilings ----------------
    const int u01 = 2 * lane;               // layer1: lanes span 64 units
    const int u02 = 2 * (lane & 15);        // layer2: 16 lanes span 32 units
    const int bh2 = (lane >> 4) * 4;        // layer2: half-warp batch split (4 each)
    const int wj1 = 4 * lane;               // layer1 weight block offset
    const int wj2 = 4 * (lane & 15);        // layer2 weight block offset

    const int gw = wid * GRID + blockIdx.x;

    for (int tau = gw; tau < NTASKS; tau += WSLOTS) {
        const float* xg = x + (size_t)tau * TB * (TT * DD);

        for (int i = lane; i < H1 * HS1; i += 32) sH1w[i] = 0.0f;
        for (int i = lane; i < H2 * HS2; i += 32) sH2w[i] = 0.0f;
        __syncwarp();

        float c1[2][TB];
        #pragma unroll
        for (int u = 0; u < 2; u++)
            #pragma unroll
            for (int b = 0; b < TB; b++) c1[u][b] = 0.0f;
        float c2[2][4];
        #pragma unroll
        for (int u = 0; u < 2; u++)
            #pragma unroll
            for (int b = 0; b < 4; b++) c2[u][b] = 0.0f;

        // prefetch x(t=0)
        float xr[2];
        #pragma unroll
        for (int j = 0; j < 2; j++) {
            int idx = 32 * j + lane;
            if (idx < DD * TB) {
                int b = idx / DD, d = idx - b * DD;
                xr[j] = xg[b * (TT * DD) + d];
            }
        }

        for (int t = 0; t < TT; t++) {
            // store x(t); prefetch x(t+1)
            #pragma unroll
            for (int j = 0; j < 2; j++) {
                int idx = 32 * j + lane;
                if (idx < DD * TB) {
                    int b = idx / DD, d = idx - b * DD;
                    sXw[d * XS + b] = xr[j];
                }
            }
            __syncwarp();
            if (t + 1 < TT) {
                #pragma unroll
                for (int j = 0; j < 2; j++) {
                    int idx = 32 * j + lane;
                    if (idx < DD * TB) {
                        int b = idx / DD, d = idx - b * DD;
                        xr[j] = xg[b * (TT * DD) + (t + 1) * DD + d];
                    }
                }
            }

            // ================= layer 1 gates =================
            u64t a1[2][4][4];
            #pragma unroll
            for (int g = 0; g < 4; g++) {
                u64t bp = lds64(&sB1[g * H1 + u01]);   // reload per step (saves regs)
                float blo, bhi; upk(bp, blo, bhi);
                u64t plo = pk2(blo, blo), phi = pk2(bhi, bhi);
                #pragma unroll
                for (int p = 0; p < 4; p++) { a1[0][g][p] = plo; a1[1][g][p] = phi; }
            }
            #pragma unroll
            for (int d = 0; d < DD; d++) {
                const float* wr = &sW1T[d * G1];
                ulonglong2 wqA = lds128(wr + wj1);        // (i0,i1),(f0,f1)
                ulonglong2 wqB = lds128(wr + 128 + wj1);  // (g0,g1),(o0,o1)
                float wi0, wi1, wf0, wf1, wg0, wg1, wo0, wo1;
                upk(wqA.x, wi0, wi1); upk(wqA.y, wf0, wf1);
                upk(wqB.x, wg0, wg1); upk(wqB.y, wo0, wo1);
                u64t wp[2][4];
                wp[0][0] = pk2(wi0, wi0); wp[1][0] = pk2(wi1, wi1);
                wp[0][1] = pk2(wf0, wf0); wp[1][1] = pk2(wf1, wf1);
                wp[0][2] = pk2(wg0, wg0); wp[1][2] = pk2(wg1, wg1);
                wp[0][3] = pk2(wo0, wo0); wp[1][3] = pk2(wo1, wo1);
                ulonglong2 xq0 = lds128(&sXw[d * XS]);      // pairs 0,1 (broadcast)
                ulonglong2 xq1 = lds128(&sXw[d * XS + 4]);  // pairs 2,3
                u64t hv[4] = { xq0.x, xq0.y, xq1.x, xq1.y };
                #pragma unroll
                for (int p = 0; p < 4; p++) {
                    #pragma unroll
                    for (int g = 0; g < 4; g++) {
                        a1[0][g][p] = fma2(wp[0][g], hv[p], a1[0][g][p]);
                        a1[1][g][p] = fma2(wp[1][g], hv[p], a1[1][g][p]);
                    }
                }
            }
            #pragma unroll 2
            for (int k = 0; k < H1; k++) {
                const float* wr = &sW1T[(DD + k) * G1];
                ulonglong2 wqA = lds128(wr + wj1);
                ulonglong2 wqB = lds128(wr + 128 + wj1);
                float wi0, wi1, wf0, wf1, wg0, wg1, wo0, wo1;
                upk(wqA.x, wi0, wi1); upk(wqA.y, wf0, wf1);
                upk(wqB.x, wg0, wg1); upk(wqB.y, wo0, wo1);
                u64t wp[2][4];
                wp[0][0] = pk2(wi0, wi0); wp[1][0] = pk2(wi1, wi1);
                wp[0][1] = pk2(wf0, wf0); wp[1][1] = pk2(wf1, wf1);
                wp[0][2] = pk2(wg0, wg0); wp[1][2] = pk2(wg1, wg1);
                wp[0][3] = pk2(wo0, wo0); wp[1][3] = pk2(wo1, wo1);
                ulonglong2 hq0 = lds128(&sH1w[k * HS1]);      // pairs 0,1 (broadcast)
                ulonglong2 hq1 = lds128(&sH1w[k * HS1 + 4]);  // pairs 2,3
                u64t hv[4] = { hq0.x, hq0.y, hq1.x, hq1.y };
                #pragma unroll
                for (int p = 0; p < 4; p++) {
                    #pragma unroll
                    for (int g = 0; g < 4; g++) {
                        a1[0][g][p] = fma2(wp[0][g], hv[p], a1[0][g][p]);
                        a1[1][g][p] = fma2(wp[1][g], hv[p], a1[1][g][p]);
                    }
                }
            }
            __syncwarp();                      // WAR on old h1

            // pointwise layer1 + write new h1
            #pragma unroll
            for (int u = 0; u < 2; u++) {
                #pragma unroll
                for (int p = 0; p < 4; p++) {
                    float gi[2], gf[2], gg[2], go[2], hh[2];
                    upk(a1[u][0][p], gi[0], gi[1]);
                    upk(a1[u][1][p], gf[0], gf[1]);
                    upk(a1[u][2][p], gg[0], gg[1]);
                    upk(a1[u][3][p], go[0], go[1]);
                    #pragma unroll
                    for (int s = 0; s < 2; s++) {
                        float ii = sig_h(gi[s]);
                        float ff = sig_h(gf[s]);
                        float g_ = tanha(gg[s]);
                        float oo = sig_h(go[s]);
                        float cc = ff * c1[u][2 * p + s] + ii * g_;
                        c1[u][2 * p + s] = cc;
                        hh[s] = oo * tanha(cc);
                    }
                    sts64(&sH1w[(u01 + u) * HS1 + 2 * p], pk2(hh[0], hh[1]));
                }
            }
            __syncwarp();                      // RAW: new h1 visible

            // ================= layer 2 gates =================
            u64t a2[2][4][2];
            #pragma unroll
            for (int g = 0; g < 4; g++) {
                u64t bp = lds64(&sB2[g * H2 + u02]);
                float blo, bhi; upk(bp, blo, bhi);
                u64t plo = pk2(blo, blo), phi = pk2(bhi, bhi);
                #pragma unroll
                for (int p = 0; p < 2; p++) { a2[0][g][p] = plo; a2[1][g][p] = phi; }
            }
            #pragma unroll 2
            for (int k = 0; k < H1; k++) {     // input = new h1
                const float* wr = &sW2T[k * G2];
                ulonglong2 wqA = lds128(wr + wj2);
                ulonglong2 wqB = lds128(wr + 64 + wj2);
                float wi0, wi1, wf0, wf1, wg0, wg1, wo0, wo1;
                upk(wqA.x, wi0, wi1); upk(wqA.y, wf0, wf1);
                upk(wqB.x, wg0, wg1); upk(wqB.y, wo0, wo1);
                u64t wp[2][4];
                wp[0][0] = pk2(wi0, wi0); wp[1][0] = pk2(wi1, wi1);
                wp[0][1] = pk2(wf0, wf0); wp[1][1] = pk2(wf1, wf1);
                wp[0][2] = pk2(wg0, wg0); wp[1][2] = pk2(wg1, wg1);
                wp[0][3] = pk2(wo0, wo0); wp[1][3] = pk2(wo1, wo1);
                ulonglong2 hq = lds128(&sH1w[k * HS1 + bh2]);  // 2 pairs (broadcast/2-way)
                u64t hv[2] = { hq.x, hq.y };
                #pragma unroll
                for (int p = 0; p < 2; p++) {
                    #pragma unroll
                    for (int g = 0; g < 4; g++) {
                        a2[0][g][p] = fma2(wp[0][g], hv[p], a2[0][g][p]);
                        a2[1][g][p] = fma2(wp[1][g], hv[p], a2[1][g][p]);
                    }
                }
            }
            #pragma unroll 2
            for (int k = 0; k < H2; k++) {     // recurrent = old h2
                const float* wr = &sW2T[(H1 + k) * G2];
                ulonglong2 wqA = lds128(wr + wj2);
                ulonglong2 wqB = lds128(wr + 64 + wj2);
                float wi0, wi1, wf0, wf1, wg0, wg1, wo0, wo1;
                upk(wqA.x, wi0, wi1); upk(wqA.y, wf0, wf1);
                upk(wqB.x, wg0, wg1); upk(wqB.y, wo0, wo1);
                u64t wp[2][4];
                wp[0][0] = pk2(wi0, wi0); wp[1][0] = pk2(wi1, wi1);
                wp[0][1] = pk2(wf0, wf0); wp[1][1] = pk2(wf1, wf1);
                wp[0][2] = pk2(wg0, wg0); wp[1][2] = pk2(wg1, wg1);
                wp[0][3] = pk2(wo0, wo0); wp[1][3] = pk2(wo1, wo1);
                ulonglong2 hq = lds128(&sH2w[k * HS2 + bh2]);
                u64t hv[2] = { hq.x, hq.y };
                #pragma unroll
                for (int p = 0; p < 2; p++) {
                    #pragma unroll
                    for (int g = 0; g < 4; g++) {
                        a2[0][g][p] = fma2(wp[0][g], hv[p], a2[0][g][p]);
                        a2[1][g][p] = fma2(wp[1][g], hv[p], a2[1][g][p]);
                    }
                }
            }
            __syncwarp();                      // WAR on old h2

            // pointwise layer2 + write new h2
            #pragma unroll
            for (int u = 0; u < 2; u++) {
                #pragma unroll
                for (int p = 0; p < 2; p++) {
                    float gi[2], gf[2], gg[2], go[2], hh[2];
                    upk(a2[u][0][p], gi[0], gi[1]);
                    upk(a2[u][1][p], gf[0], gf[1]);
                    upk(a2[u][2][p], gg[0], gg[1]);
                    upk(a2[u][3][p], go[0], go[1]);
                    #pragma unroll
                    for (int s = 0; s < 2; s++) {
                        float ii = sig_h(gi[s]);
                        float ff = sig_h(gf[s]);
                        float g_ = tanha(gg[s]);
                        float oo = sig_h(go[s]);
                        float cc = ff * c2[u][2 * p + s] + ii * g_;
                        c2[u][2 * p + s] = cc;
                        hh[s] = oo * tanha(cc);
                    }
                    sts64(&sH2w[(u02 + u) * HS2 + bh2 + 2 * p], pk2(hh[0], hh[1]));
                }
            }
            __syncwarp();                      // new h2 visible
        }

        // ================= head: dense(16)+relu -> dot(16)+sigmoid =============
        if (lane < TB) {
            const int b = lane;
            float hv[H2];
            #pragma unroll
            for (int k = 0; k < H2; k++) hv[k] = sH2w[k * HS2 + b];
            float o = __ldg(&bo[0]);
            #pragma unroll
            for (int j = 0; j < 16; j++) {
                float s = __ldg(&bd[j]);
                #pragma unroll
                for (int k = 0; k < H2; k++) s += hv[k] * __ldg(&Wd[j * H2 + k]);
                o += fmaxf(s, 0.0f) * __ldg(&Wo[j]);
            }
            out[tau * TB + b] = sigx(o);
        }
        __syncwarp();
    }
}

extern "C" void kernel_launch(void* const* d_in, const int* in_sizes, int n_in,
                              void* d_out, int out_size) {
    const float* x    = (const float*)d_in[0];
    const float* Wih1 = (const float*)d_in[1];
    const float* Whh1 = (const float*)d_in[2];
    const float* bih1 = (const float*)d_in[3];
    const float* bhh1 = (const float*)d_in[4];
    const float* Wih2 = (const float*)d_in[5];
    const float* Whh2 = (const float*)d_in[6];
    const float* bih2 = (const float*)d_in[7];
    const float* bhh2 = (const float*)d_in[8];
    const float* Wd   = (const float*)d_in[9];
    const float* bd   = (const float*)d_in[10];
    const float* Wo   = (const float*)d_in[11];
    const float* bo   = (const float*)d_in[12];
    float* out = (float*)d_out;

    static bool attr_set = false;
    if (!attr_set) {
        cudaFuncSetAttribute(momentum_lstm_kernel,
                             cudaFuncAttributeMaxDynamicSharedMemorySize, SMEM_BYTES);
        attr_set = true;
    }

    momentum_lstm_kernel<<<GRID, NT, SMEM_BYTES>>>(
        x, Wih1, Whh1, bih1, bhh1, Wih2, Whh2, bih2, bhh2, Wd, bd, Wo, bo, out);
}

// round 13
// speedup vs baseline: 1.0229x; 1.0229x over previous
#include <cuda_runtime.h>
#include <cuda_bf16.h>

// MomentumLSTM v12: v10 verbatim (best 2115us: 512 thr, 128 regs, 4 warps/SMSP,
// warp-local recurrence, f32x2 weight-dup flow) +
//  (a) t=0 peel: recurrent k-loops guarded by `if (t)`, state zeroing removed
//  (b) layer2 k-loops unrolled x4 (more LDS MLP in the low-reg-pressure phase)

#define BATCH  32768
#define TT     60
#define DD     7
#define H1     64
#define G1     256
#define H2     32
#define G2     128
#define NT     512
#define GRID   152
#define TB     8                 // batches per warp-task
#define NTASKS (BATCH / TB)      // 4096
#define WSLOTS (GRID * 16)       // 2432
#define HS1    10                // even stride: [64][10] per-warp h1 slab
#define HS2    10                // [32][10]
#define XS     8                 // [7][8]

// SMEM float offsets
#define OFF_W1T 0                // [71][256] rows 0..6 x-w, 7..70 h-w (i/f/o pre-scaled 0.5)
#define OFF_W2T 18176            // [96][128]
#define OFF_B1  30464            // [256]
#define OFF_B2  30720            // [128]
#define OFF_H1  30848            // 16 x 640
#define OFF_H2  41088            // 16 x 320
#define OFF_X   46208            // 16 x 64
#define SMEM_FLOATS 47232
#define SMEM_BYTES  (SMEM_FLOATS * 4)   // 188928

typedef unsigned long long u64t;

__device__ __forceinline__ u64t pk2(float a, float b) {
    u64t r; asm("mov.b64 %0, {%1, %2};" : "=l"(r) : "f"(a), "f"(b)); return r;
}
__device__ __forceinline__ void upk(u64t v, float& lo, float& hi) {
    asm("mov.b64 {%0, %1}, %2;" : "=f"(lo), "=f"(hi) : "l"(v));
}
__device__ __forceinline__ u64t fma2(u64t a, u64t b, u64t c) {
    u64t d; asm("fma.rn.f32x2 %0, %1, %2, %3;" : "=l"(d) : "l"(a), "l"(b), "l"(c)); return d;
}
__device__ __forceinline__ u64t lds64(const float* p) {
    return *reinterpret_cast<const u64t*>(p);
}
__device__ __forceinline__ void sts64(float* p, u64t v) {
    *reinterpret_cast<u64t*>(p) = v;
}
__device__ __forceinline__ float tanha(float x) {
    float y; asm("tanh.approx.f32 %0, %1;" : "=f"(y) : "f"(x)); return y;
}
// acc already holds x/2 (weights pre-scaled): sigmoid(x) = 0.5*tanh(x/2)+0.5
__device__ __forceinline__ float sig_h(float halfx) {
    return fmaf(0.5f, tanha(halfx), 0.5f);
}
__device__ __forceinline__ float sigx(float x) {   // exact, output only
    return __fdividef(1.0f, 1.0f + __expf(-x));
}

__global__ void __launch_bounds__(NT, 1)
momentum_lstm_kernel(const float* __restrict__ x,
                     const float* __restrict__ Wih1, const float* __restrict__ Whh1,
                     const float* __restrict__ bih1, const float* __restrict__ bhh1,
                     const float* __restrict__ Wih2, const float* __restrict__ Whh2,
                     const float* __restrict__ bih2, const float* __restrict__ bhh2,
                     const float* __restrict__ Wd,  const float* __restrict__ bd,
                     const float* __restrict__ Wo,  const float* __restrict__ bo,
                     float* __restrict__ out)
{
    extern __shared__ float sm[];
    float* sW1T = sm + OFF_W1T;
    float* sW2T = sm + OFF_W2T;
    float* sB1  = sm + OFF_B1;
    float* sB2  = sm + OFF_B2;

    const int tid  = threadIdx.x;
    const int lane = tid & 31;
    const int wid  = tid >> 5;

    float* sH1w = sm + OFF_H1 + wid * (H1 * HS1);
    float* sH2w = sm + OFF_H2 + wid * (H2 * HS2);
    float* sXw  = sm + OFF_X  + wid * 64;

    // ---------------- staging: transpose + pre-scale i/f/o rows by 0.5 ----------------
    for (int i = tid; i < DD * G1; i += NT) {
        int d = i >> 8, g = i & 255;
        float s = ((g >> 6) == 2) ? 1.0f : 0.5f;       // gate order i,f,g,o
        sW1T[d * G1 + g] = s * Wih1[g * DD + d];
    }
    for (int i = tid; i < H1 * G1; i += NT) {
        int k = i >> 8, g = i & 255;
        float s = ((g >> 6) == 2) ? 1.0f : 0.5f;
        sW1T[(DD + k) * G1 + g] = s * Whh1[g * H1 + k];
    }
    for (int i = tid; i < (H1 + H2) * G2; i += NT) {
        int k = i >> 7, g = i & 127;
        float s = ((g >> 5) == 2) ? 1.0f : 0.5f;
        sW2T[i] = s * ((k < H1) ? Wih2[g * H1 + k] : Whh2[g * H2 + (k - H1)]);
    }
    if (tid < G1) {
        float s = ((tid >> 6) == 2) ? 1.0f : 0.5f;
        sB1[tid] = s * (bih1[tid] + bhh1[tid]);
    }
    if (tid < G2) {
        float s = ((tid >> 5) == 2) ? 1.0f : 0.5f;
        sB2[tid] = s * (bih2[tid] + bhh2[tid]);
    }
    __syncthreads();

    // ---------------- warp-local tilings ----------------
    const int u01 = 2 * lane;               // layer1: lanes span 64 units
    const int u02 = 2 * (lane & 15);        // layer2: 16 lanes span 32 units
    const int bh2 = (lane >> 4) * 4;        // layer2: half-warp batch split (4 each)

    const int gw = wid * GRID + blockIdx.x;   // interleaved task id

    for (int tau = gw; tau < NTASKS; tau += WSLOTS) {
        const float* xg = x + (size_t)tau * TB * (TT * DD);

        // no state zeroing needed: t=0 skips all reads of h1/h2 (h(-1) == 0)

        float c1[2][TB];
        #pragma unroll
        for (int u = 0; u < 2; u++)
            #pragma unroll
            for (int b = 0; b < TB; b++) c1[u][b] = 0.0f;
        float c2[2][4];
        #pragma unroll
        for (int u = 0; u < 2; u++)
            #pragma unroll
            for (int b = 0; b < 4; b++) c2[u][b] = 0.0f;

        // prefetch x(t=0)
        float xr[2];
        #pragma unroll
        for (int j = 0; j < 2; j++) {
            int idx = 32 * j + lane;
            if (idx < DD * TB) {
                int b = idx / DD, d = idx - b * DD;
                xr[j] = xg[b * (TT * DD) + d];
            }
        }

        for (int t = 0; t < TT; t++) {
            // store x(t); prefetch x(t+1)
            #pragma unroll
            for (int j = 0; j < 2; j++) {
                int idx = 32 * j + lane;
                if (idx < DD * TB) {
                    int b = idx / DD, d = idx - b * DD;
                    sXw[d * XS + b] = xr[j];
                }
            }
            __syncwarp();
            if (t + 1 < TT) {
                #pragma unroll
                for (int j = 0; j < 2; j++) {
                    int idx = 32 * j + lane;
                    if (idx < DD * TB) {
                        int b = idx / DD, d = idx - b * DD;
                        xr[j] = xg[b * (TT * DD) + (t + 1) * DD + d];
                    }
                }
            }

            // ================= layer 1 gates =================
            u64t a1[2][4][4];
            #pragma unroll
            for (int g = 0; g < 4; g++) {
                u64t bp = lds64(&sB1[g * H1 + u01]);   // reload per step (saves regs)
                float blo, bhi; upk(bp, blo, bhi);
                u64t plo = pk2(blo, blo), phi = pk2(bhi, bhi);
                #pragma unroll
                for (int p = 0; p < 4; p++) { a1[0][g][p] = plo; a1[1][g][p] = phi; }
            }
            #pragma unroll
            for (int d = 0; d < DD; d++) {
                u64t wp[2][4];
                #pragma unroll
                for (int g = 0; g < 4; g++) {
                    u64t wv = lds64(&sW1T[d * G1 + g * H1 + u01]);
                    float wl, wh; upk(wv, wl, wh);
                    wp[0][g] = pk2(wl, wl); wp[1][g] = pk2(wh, wh);
                }
                #pragma unroll
                for (int p = 0; p < 4; p++) {
                    u64t xv = lds64(&sXw[d * XS + 2 * p]);
                    #pragma unroll
                    for (int g = 0; g < 4; g++) {
                        a1[0][g][p] = fma2(wp[0][g], xv, a1[0][g][p]);
                        a1[1][g][p] = fma2(wp[1][g], xv, a1[1][g][p]);
                    }
                }
            }
            if (t) {                               // h1(t-1) == 0 at t==0
                #pragma unroll 2
                for (int k = 0; k < H1; k++) {
                    u64t wp[2][4];
                    #pragma unroll
                    for (int g = 0; g < 4; g++) {
                        u64t wv = lds64(&sW1T[(DD + k) * G1 + g * H1 + u01]);
                        float wl, wh; upk(wv, wl, wh);
                        wp[0][g] = pk2(wl, wl); wp[1][g] = pk2(wh, wh);
                    }
                    #pragma unroll
                    for (int p = 0; p < 4; p++) {
                        u64t hv = lds64(&sH1w[k * HS1 + 2 * p]);
                        #pragma unroll
                        for (int g = 0; g < 4; g++) {
                            a1[0][g][p] = fma2(wp[0][g], hv, a1[0][g][p]);
                            a1[1][g][p] = fma2(wp[1][g], hv, a1[1][g][p]);
                        }
                    }
                }
            }
            __syncwarp();                      // WAR on old h1

            // pointwise layer1 + write new h1
            #pragma unroll
            for (int u = 0; u < 2; u++) {
                #pragma unroll
                for (int p = 0; p < 4; p++) {
                    float gi[2], gf[2], gg[2], go[2], hh[2];
                    upk(a1[u][0][p], gi[0], gi[1]);
                    upk(a1[u][1][p], gf[0], gf[1]);
                    upk(a1[u][2][p], gg[0], gg[1]);
                    upk(a1[u][3][p], go[0], go[1]);
                    #pragma unroll
                    for (int s = 0; s < 2; s++) {
                        float ii = sig_h(gi[s]);
                        float ff = sig_h(gf[s]);
                        float g_ = tanha(gg[s]);
                        float oo = sig_h(go[s]);
                        float cc = ff * c1[u][2 * p + s] + ii * g_;
                        c1[u][2 * p + s] = cc;
                        hh[s] = oo * tanha(cc);
                    }
                    sts64(&sH1w[(u01 + u) * HS1 + 2 * p], pk2(hh[0], hh[1]));
                }
            }
            __syncwarp();                      // RAW: new h1 visible

            // ================= layer 2 gates =================
            u64t a2[2][4][2];
            #pragma unroll
            for (int g = 0; g < 4; g++) {
                u64t bp = lds64(&sB2[g * H2 + u02]);   // reload per step
                float blo, bhi; upk(bp, blo, bhi);
                u64t plo = pk2(blo, blo), phi = pk2(bhi, bhi);
                #pragma unroll
                for (int p = 0; p < 2; p++) { a2[0][g][p] = plo; a2[1][g][p] = phi; }
            }
            #pragma unroll 4
            for (int k = 0; k < H1; k++) {     // input = new h1
                u64t wp[2][4];
                #pragma unroll
                for (int g = 0; g < 4; g++) {
                    u64t wv = lds64(&sW2T[k * G2 + g * H2 + u02]);
                    float wl, wh; upk(wv, wl, wh);
                    wp[0][g] = pk2(wl, wl); wp[1][g] = pk2(wh, wh);
                }
                #pragma unroll
                for (int p = 0; p < 2; p++) {
                    u64t hv = lds64(&sH1w[k * HS1 + bh2 + 2 * p]);
                    #pragma unroll
                    for (int g = 0; g < 4; g++) {
                        a2[0][g][p] = fma2(wp[0][g], hv, a2[0][g][p]);
                        a2[1][g][p] = fma2(wp[1][g], hv, a2[1][g][p]);
                    }
                }
            }
            if (t) {                               // h2(t-1) == 0 at t==0
                #pragma unroll 4
                for (int k = 0; k < H2; k++) {     // recurrent = old h2
                    u64t wp[2][4];
                    #pragma unroll
                    for (int g = 0; g < 4; g++) {
                        u64t wv = lds64(&sW2T[(H1 + k) * G2 + g * H2 + u02]);
                        float wl, wh; upk(wv, wl, wh);
                        wp[0][g] = pk2(wl, wl); wp[1][g] = pk2(wh, wh);
                    }
                    #pragma unroll
                    for (int p = 0; p < 2; p++) {
                        u64t hv = lds64(&sH2w[k * HS2 + bh2 + 2 * p]);
                        #pragma unroll
                        for (int g = 0; g < 4; g++) {
                            a2[0][g][p] = fma2(wp[0][g], hv, a2[0][g][p]);
                            a2[1][g][p] = fma2(wp[1][g], hv, a2[1][g][p]);
                        }
                    }
                }
            }
            __syncwarp();                      // WAR on old h2

            // pointwise layer2 + write new h2
            #pragma unroll
            for (int u = 0; u < 2; u++) {
                #pragma unroll
                for (int p = 0; p < 2; p++) {
                    float gi[2], gf[2], gg[2], go[2], hh[2];
                    upk(a2[u][0][p], gi[0], gi[1]);
                    upk(a2[u][1][p], gf[0], gf[1]);
                    upk(a2[u][2][p], gg[0], gg[1]);
                    upk(a2[u][3][p], go[0], go[1]);
                    #pragma unroll
                    for (int s = 0; s < 2; s++) {
                        float ii = sig_h(gi[s]);
                        float ff = sig_h(gf[s]);
                        float g_ = tanha(gg[s]);
                        float oo = sig_h(go[s]);
                        float cc = ff * c2[u][2 * p + s] + ii * g_;
                        c2[u][2 * p + s] = cc;
                        hh[s] = oo * tanha(cc);
                    }
                    sts64(&sH2w[(u02 + u) * HS2 + bh2 + 2 * p], pk2(hh[0], hh[1]));
                }
            }
            __syncwarp();                      // new h2 visible
        }

        // ================= head: dense(16)+relu -> dot(16)+sigmoid =============
        if (lane < TB) {
            const int b = lane;
            float hv[H2];
            #pragma unroll
            for (int k = 0; k < H2; k++) hv[k] = sH2w[k * HS2 + b];
            float o = __ldg(&bo[0]);
            #pragma unroll
            for (int j = 0; j < 16; j++) {
                float s = __ldg(&bd[j]);
                #pragma unroll
                for (int k = 0; k < H2; k++) s += hv[k] * __ldg(&Wd[j * H2 + k]);
                o += fmaxf(s, 0.0f) * __ldg(&Wo[j]);
            }
            out[tau * TB + b] = sigx(o);
        }
        __syncwarp();
    }
}

extern "C" void kernel_launch(void* const* d_in, const int* in_sizes, int n_in,
                              void* d_out, int out_size) {
    const float* x    = (const float*)d_in[0];
    const float* Wih1 = (const float*)d_in[1];
    const float* Whh1 = (const float*)d_in[2];
    const float* bih1 = (const float*)d_in[3];
    const float* bhh1 = (const float*)d_in[4];
    const float* Wih2 = (const float*)d_in[5];
    const float* Whh2 = (const float*)d_in[6];
    const float* bih2 = (const float*)d_in[7];
    const float* bhh2 = (const float*)d_in[8];
    const float* Wd   = (const float*)d_in[9];
    const float* bd   = (const float*)d_in[10];
    const float* Wo   = (const float*)d_in[11];
    const float* bo   = (const float*)d_in[12];
    float* out = (float*)d_out;

    static bool attr_set = false;
    if (!attr_set) {
        cudaFuncSetAttribute(momentum_lstm_kernel,
                             cudaFuncAttributeMaxDynamicSharedMemorySize, SMEM_BYTES);
        attr_set = true;
    }

    momentum_lstm_kernel<<<GRID, NT, SMEM_BYTES>>>(
        x, Wih1, Whh1, bih1, bhh1, Wih2, Whh2, bih2, bhh2, Wd, bd, Wo, bo, out);
}

// round 14
// speedup vs baseline: 1.0298x; 1.0067x over previous
#include <cuda_runtime.h>
#include <cuda_bf16.h>

// MomentumLSTM v13: v12 base (2087us) + MUFU/FMA overlap:
// layer2-RECURRENT gate loop made branch-free (h2 zeroed per task, no `if (t)`)
// and fused into one straight-line region with pointwise-L1, so ptxas interleaves
// its LDS/FFMA2 stream into the MUFU dependency chains. Order per step:
//   L1 gates -> sync -> [pointwise-L1 || L2-recurrent] -> sync -> L2-input ->
//   pointwise-L2 -> sync

#define BATCH  32768
#define TT     60
#define DD     7
#define H1     64
#define G1     256
#define H2     32
#define G2     128
#define NT     512
#define GRID   152
#define TB     8                 // batches per warp-task
#define NTASKS (BATCH / TB)      // 4096
#define WSLOTS (GRID * 16)       // 2432
#define HS1    10                // even stride: [64][10] per-warp h1 slab
#define HS2    10                // [32][10]
#define XS     8                 // [7][8]

// SMEM float offsets
#define OFF_W1T 0                // [71][256] rows 0..6 x-w, 7..70 h-w (i/f/o pre-scaled 0.5)
#define OFF_W2T 18176            // [96][128]
#define OFF_B1  30464            // [256]
#define OFF_B2  30720            // [128]
#define OFF_H1  30848            // 16 x 640
#define OFF_H2  41088            // 16 x 320
#define OFF_X   46208            // 16 x 64
#define SMEM_FLOATS 47232
#define SMEM_BYTES  (SMEM_FLOATS * 4)   // 188928

typedef unsigned long long u64t;

__device__ __forceinline__ u64t pk2(float a, float b) {
    u64t r; asm("mov.b64 %0, {%1, %2};" : "=l"(r) : "f"(a), "f"(b)); return r;
}
__device__ __forceinline__ void upk(u64t v, float& lo, float& hi) {
    asm("mov.b64 {%0, %1}, %2;" : "=f"(lo), "=f"(hi) : "l"(v));
}
__device__ __forceinline__ u64t fma2(u64t a, u64t b, u64t c) {
    u64t d; asm("fma.rn.f32x2 %0, %1, %2, %3;" : "=l"(d) : "l"(a), "l"(b), "l"(c)); return d;
}
__device__ __forceinline__ u64t lds64(const float* p) {
    return *reinterpret_cast<const u64t*>(p);
}
__device__ __forceinline__ void sts64(float* p, u64t v) {
    *reinterpret_cast<u64t*>(p) = v;
}
__device__ __forceinline__ float tanha(float x) {
    float y; asm("tanh.approx.f32 %0, %1;" : "=f"(y) : "f"(x)); return y;
}
// acc already holds x/2 (weights pre-scaled): sigmoid(x) = 0.5*tanh(x/2)+0.5
__device__ __forceinline__ float sig_h(float halfx) {
    return fmaf(0.5f, tanha(halfx), 0.5f);
}
__device__ __forceinline__ float sigx(float x) {   // exact, output only
    return __fdividef(1.0f, 1.0f + __expf(-x));
}

__global__ void __launch_bounds__(NT, 1)
momentum_lstm_kernel(const float* __restrict__ x,
                     const float* __restrict__ Wih1, const float* __restrict__ Whh1,
                     const float* __restrict__ bih1, const float* __restrict__ bhh1,
                     const float* __restrict__ Wih2, const float* __restrict__ Whh2,
                     const float* __restrict__ bih2, const float* __restrict__ bhh2,
                     const float* __restrict__ Wd,  const float* __restrict__ bd,
                     const float* __restrict__ Wo,  const float* __restrict__ bo,
                     float* __restrict__ out)
{
    extern __shared__ float sm[];
    float* sW1T = sm + OFF_W1T;
    float* sW2T = sm + OFF_W2T;
    float* sB1  = sm + OFF_B1;
    float* sB2  = sm + OFF_B2;

    const int tid  = threadIdx.x;
    const int lane = tid & 31;
    const int wid  = tid >> 5;

    float* sH1w = sm + OFF_H1 + wid * (H1 * HS1);
    float* sH2w = sm + OFF_H2 + wid * (H2 * HS2);
    float* sXw  = sm + OFF_X  + wid * 64;

    // ---------------- staging: transpose + pre-scale i/f/o rows by 0.5 ----------------
    for (int i = tid; i < DD * G1; i += NT) {
        int d = i >> 8, g = i & 255;
        float s = ((g >> 6) == 2) ? 1.0f : 0.5f;       // gate order i,f,g,o
        sW1T[d * G1 + g] = s * Wih1[g * DD + d];
    }
    for (int i = tid; i < H1 * G1; i += NT) {
        int k = i >> 8, g = i & 255;
        float s = ((g >> 6) == 2) ? 1.0f : 0.5f;
        sW1T[(DD + k) * G1 + g] = s * Whh1[g * H1 + k];
    }
    for (int i = tid; i < (H1 + H2) * G2; i += NT) {
        int k = i >> 7, g = i & 127;
        float s = ((g >> 5) == 2) ? 1.0f : 0.5f;
        sW2T[i] = s * ((k < H1) ? Wih2[g * H1 + k] : Whh2[g * H2 + (k - H1)]);
    }
    if (tid < G1) {
        float s = ((tid >> 6) == 2) ? 1.0f : 0.5f;
        sB1[tid] = s * (bih1[tid] + bhh1[tid]);
    }
    if (tid < G2) {
        float s = ((tid >> 5) == 2) ? 1.0f : 0.5f;
        sB2[tid] = s * (bih2[tid] + bhh2[tid]);
    }
    __syncthreads();

    // ---------------- warp-local tilings ----------------
    const int u01 = 2 * lane;               // layer1: lanes span 64 units
    const int u02 = 2 * (lane & 15);        // layer2: 16 lanes span 32 units
    const int bh2 = (lane >> 4) * 4;        // layer2: half-warp batch split (4 each)

    const int gw = wid * GRID + blockIdx.x;   // interleaved task id

    for (int tau = gw; tau < NTASKS; tau += WSLOTS) {
        const float* xg = x + (size_t)tau * TB * (TT * DD);

        // zero h2 slab only (L2-recurrent loop is branch-free, reads zeros at t=0;
        // L1-recurrent stays peeled behind `if (t)`)
        for (int i = lane; i < H2 * HS2; i += 32) sH2w[i] = 0.0f;
        __syncwarp();

        float c1[2][TB];
        #pragma unroll
        for (int u = 0; u < 2; u++)
            #pragma unroll
            for (int b = 0; b < TB; b++) c1[u][b] = 0.0f;
        float c2[2][4];
        #pragma unroll
        for (int u = 0; u < 2; u++)
            #pragma unroll
            for (int b = 0; b < 4; b++) c2[u][b] = 0.0f;

        // prefetch x(t=0)
        float xr[2];
        #pragma unroll
        for (int j = 0; j < 2; j++) {
            int idx = 32 * j + lane;
            if (idx < DD * TB) {
                int b = idx / DD, d = idx - b * DD;
                xr[j] = xg[b * (TT * DD) + d];
            }
        }

        for (int t = 0; t < TT; t++) {
            // store x(t); prefetch x(t+1)
            #pragma unroll
            for (int j = 0; j < 2; j++) {
                int idx = 32 * j + lane;
                if (idx < DD * TB) {
                    int b = idx / DD, d = idx - b * DD;
                    sXw[d * XS + b] = xr[j];
                }
            }
            __syncwarp();
            if (t + 1 < TT) {
                #pragma unroll
                for (int j = 0; j < 2; j++) {
                    int idx = 32 * j + lane;
                    if (idx < DD * TB) {
                        int b = idx / DD, d = idx - b * DD;
                        xr[j] = xg[b * (TT * DD) + (t + 1) * DD + d];
                    }
                }
            }

            // ================= layer 1 gates =================
            u64t a1[2][4][4];
            #pragma unroll
            for (int g = 0; g < 4; g++) {
                u64t bp = lds64(&sB1[g * H1 + u01]);
                float blo, bhi; upk(bp, blo, bhi);
                u64t plo = pk2(blo, blo), phi = pk2(bhi, bhi);
                #pragma unroll
                for (int p = 0; p < 4; p++) { a1[0][g][p] = plo; a1[1][g][p] = phi; }
            }
            #pragma unroll
            for (int d = 0; d < DD; d++) {
                u64t wp[2][4];
                #pragma unroll
                for (int g = 0; g < 4; g++) {
                    u64t wv = lds64(&sW1T[d * G1 + g * H1 + u01]);
                    float wl, wh; upk(wv, wl, wh);
                    wp[0][g] = pk2(wl, wl); wp[1][g] = pk2(wh, wh);
                }
                #pragma unroll
                for (int p = 0; p < 4; p++) {
                    u64t xv = lds64(&sXw[d * XS + 2 * p]);
                    #pragma unroll
                    for (int g = 0; g < 4; g++) {
                        a1[0][g][p] = fma2(wp[0][g], xv, a1[0][g][p]);
                        a1[1][g][p] = fma2(wp[1][g], xv, a1[1][g][p]);
                    }
                }
            }
            if (t) {                               // h1(t-1) == 0 at t==0
                #pragma unroll 2
                for (int k = 0; k < H1; k++) {
                    u64t wp[2][4];
                    #pragma unroll
                    for (int g = 0; g < 4; g++) {
                        u64t wv = lds64(&sW1T[(DD + k) * G1 + g * H1 + u01]);
                        float wl, wh; upk(wv, wl, wh);
                        wp[0][g] = pk2(wl, wl); wp[1][g] = pk2(wh, wh);
                    }
                    #pragma unroll
                    for (int p = 0; p < 4; p++) {
                        u64t hv = lds64(&sH1w[k * HS1 + 2 * p]);
                        #pragma unroll
                        for (int g = 0; g < 4; g++) {
                            a1[0][g][p] = fma2(wp[0][g], hv, a1[0][g][p]);
                            a1[1][g][p] = fma2(wp[1][g], hv, a1[1][g][p]);
                        }
                    }
                }
            }
            __syncwarp();                      // WAR on old h1

            // ====== FUSED region: pointwise-L1 (MUFU) || layer2-recurrent (FMA) ======
            // a2 bias init
            u64t a2[2][4][2];
            #pragma unroll
            for (int g = 0; g < 4; g++) {
                u64t bp = lds64(&sB2[g * H2 + u02]);
                float blo, bhi; upk(bp, blo, bhi);
                u64t plo = pk2(blo, blo), phi = pk2(bhi, bhi);
                #pragma unroll
                for (int p = 0; p < 2; p++) { a2[0][g][p] = plo; a2[1][g][p] = phi; }
            }
            // pointwise layer1 + write new h1 (MUFU-heavy)
            #pragma unroll
            for (int u = 0; u < 2; u++) {
                #pragma unroll
                for (int p = 0; p < 4; p++) {
                    float gi[2], gf[2], gg[2], go[2], hh[2];
                    upk(a1[u][0][p], gi[0], gi[1]);
                    upk(a1[u][1][p], gf[0], gf[1]);
                    upk(a1[u][2][p], gg[0], gg[1]);
                    upk(a1[u][3][p], go[0], go[1]);
                    #pragma unroll
                    for (int s = 0; s < 2; s++) {
                        float ii = sig_h(gi[s]);
                        float ff = sig_h(gf[s]);
                        float g_ = tanha(gg[s]);
                        float oo = sig_h(go[s]);
                        float cc = ff * c1[u][2 * p + s] + ii * g_;
                        c1[u][2 * p + s] = cc;
                        hh[s] = oo * tanha(cc);
                    }
                    sts64(&sH1w[(u01 + u) * HS1 + 2 * p], pk2(hh[0], hh[1]));
                }
            }
            // layer2 recurrent gates (reads OLD h2 — independent of pointwise-L1;
            // branch-free so ptxas can interleave with the MUFU chains above)
            #pragma unroll 4
            for (int k = 0; k < H2; k++) {
                u64t wp[2][4];
                #pragma unroll
                for (int g = 0; g < 4; g++) {
                    u64t wv = lds64(&sW2T[(H1 + k) * G2 + g * H2 + u02]);
                    float wl, wh; upk(wv, wl, wh);
                    wp[0][g] = pk2(wl, wl); wp[1][g] = pk2(wh, wh);
                }
                #pragma unroll
                for (int p = 0; p < 2; p++) {
                    u64t hv = lds64(&sH2w[k * HS2 + bh2 + 2 * p]);
                    #pragma unroll
                    for (int g = 0; g < 4; g++) {
                        a2[0][g][p] = fma2(wp[0][g], hv, a2[0][g][p]);
                        a2[1][g][p] = fma2(wp[1][g], hv, a2[1][g][p]);
                    }
                }
            }
            __syncwarp();    // new h1 visible (RAW); all old-h2 reads retired (WAR)

            // ================= layer2 input gates (new h1) =================
            #pragma unroll 4
            for (int k = 0; k < H1; k++) {
                u64t wp[2][4];
                #pragma unroll
                for (int g = 0; g < 4; g++) {
                    u64t wv = lds64(&sW2T[k * G2 + g * H2 + u02]);
                    float wl, wh; upk(wv, wl, wh);
                    wp[0][g] = pk2(wl, wl); wp[1][g] = pk2(wh, wh);
                }
                #pragma unroll
                for (int p = 0; p < 2; p++) {
                    u64t hv = lds64(&sH1w[k * HS1 + bh2 + 2 * p]);
                    #pragma unroll
                    for (int g = 0; g < 4; g++) {
                        a2[0][g][p] = fma2(wp[0][g], hv, a2[0][g][p]);
                        a2[1][g][p] = fma2(wp[1][g], hv, a2[1][g][p]);
                    }
                }
            }

            // pointwise layer2 + write new h2
            #pragma unroll
            for (int u = 0; u < 2; u++) {
                #pragma unroll
                for (int p = 0; p < 2; p++) {
                    float gi[2], gf[2], gg[2], go[2], hh[2];
                    upk(a2[u][0][p], gi[0], gi[1]);
                    upk(a2[u][1][p], gf[0], gf[1]);
                    upk(a2[u][2][p], gg[0], gg[1]);
                    upk(a2[u][3][p], go[0], go[1]);
                    #pragma unroll
                    for (int s = 0; s < 2; s++) {
                        float ii = sig_h(gi[s]);
                        float ff = sig_h(gf[s]);
                        float g_ = tanha(gg[s]);
                        float oo = sig_h(go[s]);
                        float cc = ff * c2[u][2 * p + s] + ii * g_;
                        c2[u][2 * p + s] = cc;
                        hh[s] = oo * tanha(cc);
                    }
                    sts64(&sH2w[(u02 + u) * HS2 + bh2 + 2 * p], pk2(hh[0], hh[1]));
                }
            }
            __syncwarp();                      // new h2 visible
        }

        // ================= head: dense(16)+relu -> dot(16)+sigmoid =============
        if (lane < TB) {
            const int b = lane;
            float hv[H2];
            #pragma unroll
            for (int k = 0; k < H2; k++) hv[k] = sH2w[k * HS2 + b];
            float o = __ldg(&bo[0]);
            #pragma unroll
            for (int j = 0; j < 16; j++) {
                float s = __ldg(&bd[j]);
                #pragma unroll
                for (int k = 0; k < H2; k++) s += hv[k] * __ldg(&Wd[j * H2 + k]);
                o += fmaxf(s, 0.0f) * __ldg(&Wo[j]);
            }
            out[tau * TB + b] = sigx(o);
        }
        __syncwarp();                          // head reads done before next-task zeroing
    }
}

extern "C" void kernel_launch(void* const* d_in, const int* in_sizes, int n_in,
                              void* d_out, int out_size) {
    const float* x    = (const float*)d_in[0];
    const float* Wih1 = (const float*)d_in[1];
    const float* Whh1 = (const float*)d_in[2];
    const float* bih1 = (const float*)d_in[3];
    const float* bhh1 = (const float*)d_in[4];
    const float* Wih2 = (const float*)d_in[5];
    const float* Whh2 = (const float*)d_in[6];
    const float* bih2 = (const float*)d_in[7];
    const float* bhh2 = (const float*)d_in[8];
    const float* Wd   = (const float*)d_in[9];
    const float* bd   = (const float*)d_in[10];
    const float* Wo   = (const float*)d_in[11];
    const float* bo   = (const float*)d_in[12];
    float* out = (float*)d_out;

    static bool attr_set = false;
    if (!attr_set) {
        cudaFuncSetAttribute(momentum_lstm_kernel,
                             cudaFuncAttributeMaxDynamicSharedMemorySize, SMEM_BYTES);
        attr_set = true;
    }

    momentum_lstm_kernel<<<GRID, NT, SMEM_BYTES>>>(
        x, Wih1, Whh1, bih1, bhh1, Wih2, Whh2, bih2, bhh2, Wd, bd, Wo, bo, out);
}